// round 14
// baseline (speedup 1.0000x reference)
#include <cuda_runtime.h>
#include <cuda_fp16.h>
#include <cstdint>

#define N_USERS  40000
#define NTOT     100000
#define IN_DIM   128
#define HID      256
#define OUT_DIM  256
#define N_EDGES  600000

// Scratch (allocation-free rule: device globals)
__device__ float  g_P  [(size_t)NTOT * IN_DIM];   // A @ feat
__device__ float  g_h  [(size_t)NTOT * HID];      // relu([P|F]@[W0;Wres] + rowsum*b0)
__device__ __half g_x2h[(size_t)NTOT * OUT_DIM];  // h @ W1 + b1, fp16 for cheap gather
__device__ float  g_rsum[NTOT];                   // A @ 1
__device__ float  g_WhT[HID * 256];               // [n][k]: k<128 -> W0[k][n], else Wres[k-128][n]
__device__ float  g_W1T[OUT_DIM * HID];           // W1^T, tf32
__device__ int    g_rcnt [NTOT];
__device__ int    g_rcnt2[NTOT];
__device__ int    g_rptr [NTOT + 1];
__device__ int    g_scol[N_EDGES];
__device__ float  g_sval[N_EDGES];

__device__ __forceinline__ float to_tf32(float x) {
    uint32_t u;
    asm("cvt.rna.tf32.f32 %0, %1;" : "=r"(u) : "f"(x));
    return __uint_as_float(u);
}
__device__ __forceinline__ uint32_t tf32u(float x) {
    uint32_t u;
    asm("cvt.rna.tf32.f32 %0, %1;" : "=r"(u) : "f"(x));
    return u;
}
__device__ __forceinline__ void mma_tf32(float* c, const uint32_t* a, const uint32_t* b) {
    asm volatile(
        "mma.sync.aligned.m16n8k8.row.col.f32.tf32.tf32.f32 "
        "{%0,%1,%2,%3}, {%4,%5,%6,%7}, {%8,%9}, {%0,%1,%2,%3};"
        : "+f"(c[0]), "+f"(c[1]), "+f"(c[2]), "+f"(c[3])
        : "r"(a[0]), "r"(a[1]), "r"(a[2]), "r"(a[3]), "r"(b[0]), "r"(b[1]));
}
__device__ __forceinline__ uint32_t smem_u32(const void* p) {
    uint32_t a;
    asm("{ .reg .u64 t; cvta.to.shared.u64 t, %1; cvt.u32.u64 %0, t; }" : "=r"(a) : "l"(p));
    return a;
}
__device__ __forceinline__ void cp16(uint32_t dst, const void* src, bool pred) {
    int sz = pred ? 16 : 0;
    asm volatile("cp.async.ca.shared.global [%0], [%1], 16, %2;"
                 :: "r"(dst), "l"(src), "r"(sz) : "memory");
}
__device__ __forceinline__ void cp_commit() {
    asm volatile("cp.async.commit_group;" ::: "memory");
}
__device__ __forceinline__ void cp_wait1() {
    asm volatile("cp.async.wait_group 1;" ::: "memory");
}
__device__ __forceinline__ void cp_wait0() {
    asm volatile("cp.async.wait_group 0;" ::: "memory");
}

#define PAD 36
#define TILEF (128 * PAD)
#define G_SMEM (4 * TILEF * 4)   // 73728 B -> 2 CTAs/SM (128-thread CTAs)

// ---------------------------------------------------------------------------
// Weight prep + zero g_rcnt
// ---------------------------------------------------------------------------
__global__ void transpose_weights(const float* __restrict__ W0,
                                  const float* __restrict__ Wres,
                                  const float* __restrict__ W1) {
    int idx = blockIdx.x * 256 + threadIdx.x;
    if (idx < IN_DIM * HID) {
        int k = idx / HID, n = idx % HID;
        g_WhT[n * 256 + k]       = to_tf32(W0[idx]);
        g_WhT[n * 256 + 128 + k] = to_tf32(Wres[idx]);
    }
    if (idx < HID * OUT_DIM) {
        int k = idx / OUT_DIM, n = idx % OUT_DIM;
        g_W1T[n * HID + k] = to_tf32(W1[idx]);
    }
    for (int i = idx; i < NTOT; i += 256 * 256) g_rcnt[i] = 0;
}

// ---------------------------------------------------------------------------
// CSR build
// ---------------------------------------------------------------------------
__global__ __launch_bounds__(256) void row_hist(const int* __restrict__ rows) {
    int e = blockIdx.x * 256 + threadIdx.x;
    if (e < N_EDGES) atomicAdd(&g_rcnt[rows[e]], 1);
}

#define CHUNK 98
__global__ __launch_bounds__(1024) void row_scan() {
    __shared__ int ssum[1024];
    const int tid = threadIdx.x;
    const int base = tid * CHUNK;
    int s = 0;
    #pragma unroll 7
    for (int i = 0; i < CHUNK; i++) {
        int idx = base + i;
        if (idx < NTOT) { s += g_rcnt[idx]; g_rcnt2[idx] = 0; }
    }
    ssum[tid] = s;
    __syncthreads();
    for (int d = 1; d < 1024; d <<= 1) {
        int o = (tid >= d) ? ssum[tid - d] : 0;
        __syncthreads();
        ssum[tid] += o;
        __syncthreads();
    }
    int run = ssum[tid] - s;
    #pragma unroll 7
    for (int i = 0; i < CHUNK; i++) {
        int idx = base + i;
        if (idx < NTOT) {
            g_rptr[idx] = run;
            run += g_rcnt[idx];
        }
    }
    if (tid == 1023) g_rptr[NTOT] = ssum[1023];
}

__global__ __launch_bounds__(256) void edge_scatter(
    const int* __restrict__ rows, const int* __restrict__ cols,
    const float* __restrict__ vals) {
    int e = blockIdx.x * 256 + threadIdx.x;
    if (e >= N_EDGES) return;
    int r = rows[e];
    int pos = g_rptr[r] + atomicAdd(&g_rcnt2[r], 1);
    g_scol[pos] = cols[e];
    g_sval[pos] = vals[e];
}

// ---------------------------------------------------------------------------
// spmmP: P = A @ feat (float4 per lane), rowsum = A @ 1. Warp per row.
// ---------------------------------------------------------------------------
__global__ __launch_bounds__(256) void spmm_feat(
    const float* __restrict__ uf, const float* __restrict__ itf)
{
    const int row = blockIdx.x * 8 + (threadIdx.x >> 5);
    if (row >= NTOT) return;
    const int lane = threadIdx.x & 31;
    int e = g_rptr[row];
    const int e1 = g_rptr[row + 1];

    float4 acc = make_float4(0.f, 0.f, 0.f, 0.f);
    float rs = 0.f;

    for (; e + 4 <= e1; e += 4) {
        int   c[4];
        float v[4];
        #pragma unroll
        for (int q = 0; q < 4; q++) { c[q] = g_scol[e + q]; v[q] = g_sval[e + q]; }
        float4 x[4];
        #pragma unroll
        for (int q = 0; q < 4; q++) {
            const float* bp = (c[q] < N_USERS) ? uf + (size_t)c[q] * IN_DIM
                                               : itf + (size_t)(c[q] - N_USERS) * IN_DIM;
            x[q] = __ldg((const float4*)bp + lane);
        }
        #pragma unroll
        for (int q = 0; q < 4; q++) {
            acc.x += v[q] * x[q].x; acc.y += v[q] * x[q].y;
            acc.z += v[q] * x[q].z; acc.w += v[q] * x[q].w;
            rs += v[q];
        }
    }
    for (; e < e1; e++) {
        const int c = g_scol[e];
        const float v = g_sval[e];
        const float* bp = (c < N_USERS) ? uf + (size_t)c * IN_DIM
                                        : itf + (size_t)(c - N_USERS) * IN_DIM;
        float4 x = __ldg((const float4*)bp + lane);
        acc.x += v * x.x; acc.y += v * x.y; acc.z += v * x.z; acc.w += v * x.w;
        rs += v;
    }

    ((float4*)(g_P + (size_t)row * IN_DIM))[lane] = acc;
    if (lane == 0) g_rsum[row] = rs;
}

// ---------------------------------------------------------------------------
// gemm_h (tf32 mma, BM=128 BN=128 grid(2,·), 128 thr, warp tile 64x64):
//   h = relu([P|F] @ WhT + rowsum*b0)
// ---------------------------------------------------------------------------
__global__ __launch_bounds__(128, 2) void gemmh_mma(
    const float* __restrict__ uf, const float* __restrict__ itf,
    const float* __restrict__ b0)
{
    extern __shared__ float smem[];
    float* Asb[2] = { smem, smem + TILEF };
    float* Bsb[2] = { smem + 2 * TILEF, smem + 3 * TILEF };
    const uint32_t sb = smem_u32(smem);

    const int tid = threadIdx.x, lane = tid & 31, wid = tid >> 5;   // 4 warps
    const int wm = (wid & 1) * 64, wn = (wid >> 1) * 64;
    const int nblk = blockIdx.x;                 // 0..1
    const int bm = blockIdx.y * 128;
    const int g = lane >> 2, t = lane & 3;
    const int lr = tid >> 3;                     // 0..15
    const int lc4 = (tid & 7) * 4;

    float acc[4][8][4];
    #pragma unroll
    for (int i = 0; i < 4; i++)
        #pragma unroll
        for (int j = 0; j < 8; j++)
            #pragma unroll
            for (int q = 0; q < 4; q++) acc[i][j][q] = 0.f;

    const int NC = 8;

    auto issue = [&](int ck, int p) {
        uint32_t a_s = sb + (uint32_t)((Asb[p] - smem) * 4);
        uint32_t b_s = sb + (uint32_t)((Bsb[p] - smem) * 4);
        #pragma unroll
        for (int i = 0; i < 8; i++) {            // A: 128x32, 8 rows/thread
            int r = i * 16 + lr;
            int rg = bm + r;
            bool ok = rg < NTOT;
            const float* src;
            if (ck < 4) {
                src = ok ? g_P + (size_t)rg * IN_DIM + ck * 32 + lc4 : g_P;
            } else {
                int kf = (ck - 4) * 32 + lc4;
                if (rg < N_USERS)      src = uf + (size_t)rg * IN_DIM + kf;
                else if (ok)           src = itf + (size_t)(rg - N_USERS) * IN_DIM + kf;
                else                   src = uf;
            }
            cp16(a_s + (uint32_t)(r * PAD + lc4) * 4, src, ok);
        }
        #pragma unroll
        for (int i = 0; i < 8; i++) {            // B: 128x32
            int r = i * 16 + lr;
            cp16(b_s + (uint32_t)(r * PAD + lc4) * 4,
                 g_WhT + (size_t)(nblk * 128 + r) * 256 + ck * 32 + lc4, true);
        }
        cp_commit();
    };

    issue(0, 0);
    for (int ck = 0; ck < NC; ck++) {
        const int p = ck & 1;
        if (ck + 1 < NC) { issue(ck + 1, p ^ 1); cp_wait1(); }
        else             { cp_wait0(); }
        __syncthreads();
        float* As = Asb[p];
        float* Bs = Bsb[p];
        #pragma unroll
        for (int kk = 0; kk < 4; kk++) {
            const int kb = kk * 8;
            uint32_t a[4][4];
            #pragma unroll
            for (int fm = 0; fm < 4; fm++) {
                int r0 = wm + fm * 16 + g;
                a[fm][0] = tf32u(As[r0 * PAD + kb + t]);
                a[fm][1] = tf32u(As[(r0 + 8) * PAD + kb + t]);
                a[fm][2] = tf32u(As[r0 * PAD + kb + t + 4]);
                a[fm][3] = tf32u(As[(r0 + 8) * PAD + kb + t + 4]);
            }
            #pragma unroll
            for (int nf = 0; nf < 8; nf++) {
                uint32_t b[2];
                int rn = wn + nf * 8 + g;
                b[0] = __float_as_uint(Bs[rn * PAD + kb + t]);
                b[1] = __float_as_uint(Bs[rn * PAD + kb + t + 4]);
                #pragma unroll
                for (int fm = 0; fm < 4; fm++)
                    mma_tf32(acc[fm][nf], a[fm], b);
            }
        }
        __syncthreads();
    }

    const int cbase = nblk * 128 + wn;
    #pragma unroll
    for (int fm = 0; fm < 4; fm++) {
        int row = bm + wm + fm * 16 + g;
        float rs0 = (row < NTOT)     ? __ldg(g_rsum + row)     : 0.f;
        float rs1 = (row + 8 < NTOT) ? __ldg(g_rsum + row + 8) : 0.f;
        #pragma unroll
        for (int nf = 0; nf < 8; nf++) {
            int col = cbase + nf * 8 + 2 * t;
            float bv0 = __ldg(b0 + col), bv1 = __ldg(b0 + col + 1);
            if (row < NTOT) {
                float o0 = to_tf32(fmaxf(acc[fm][nf][0] + rs0 * bv0, 0.f));
                float o1 = to_tf32(fmaxf(acc[fm][nf][1] + rs0 * bv1, 0.f));
                *(float2*)(g_h + (size_t)row * 256 + col) = make_float2(o0, o1);
            }
            if (row + 8 < NTOT) {
                float o2 = to_tf32(fmaxf(acc[fm][nf][2] + rs1 * bv0, 0.f));
                float o3 = to_tf32(fmaxf(acc[fm][nf][3] + rs1 * bv1, 0.f));
                *(float2*)(g_h + (size_t)(row + 8) * 256 + col) = make_float2(o2, o3);
            }
        }
    }
}

// ---------------------------------------------------------------------------
// GEMM1 (tf32 mma, BM=128 BN=128 grid(2,·), 128 thr, warp tile 64x64):
//   x2h = fp16(h @ W1 + b1)
// ---------------------------------------------------------------------------
__global__ __launch_bounds__(128, 2) void gemm1_mma(const float* __restrict__ b1)
{
    extern __shared__ float smem[];
    float* Asb[2] = { smem, smem + TILEF };
    float* Bsb[2] = { smem + 2 * TILEF, smem + 3 * TILEF };
    const uint32_t sb = smem_u32(smem);

    const int tid = threadIdx.x, lane = tid & 31, wid = tid >> 5;
    const int wm = (wid & 1) * 64, wn = (wid >> 1) * 64;
    const int nblk = blockIdx.x;                 // 0..1
    const int bm = blockIdx.y * 128;
    const int g = lane >> 2, t = lane & 3;
    const int lr = tid >> 3;
    const int lc4 = (tid & 7) * 4;

    float acc[4][8][4];
    #pragma unroll
    for (int i = 0; i < 4; i++)
        #pragma unroll
        for (int j = 0; j < 8; j++)
            #pragma unroll
            for (int q = 0; q < 4; q++) acc[i][j][q] = 0.f;

    const int NC = HID / 32;  // 8

    auto issue = [&](int ck, int p) {
        const int k0 = ck * 32;
        uint32_t a_s = sb + (uint32_t)((Asb[p] - smem) * 4);
        uint32_t b_s = sb + (uint32_t)((Bsb[p] - smem) * 4);
        #pragma unroll
        for (int i = 0; i < 8; i++) {
            int r = i * 16 + lr;
            int rg = bm + r;
            bool ok = rg < NTOT;
            const float* src = ok ? g_h + (size_t)rg * HID + k0 + lc4 : g_h;
            cp16(a_s + (uint32_t)(r * PAD + lc4) * 4, src, ok);
        }
        #pragma unroll
        for (int i = 0; i < 8; i++) {
            int r = i * 16 + lr;
            cp16(b_s + (uint32_t)(r * PAD + lc4) * 4,
                 g_W1T + (size_t)(nblk * 128 + r) * HID + k0 + lc4, true);
        }
        cp_commit();
    };

    issue(0, 0);
    for (int ck = 0; ck < NC; ck++) {
        const int p = ck & 1;
        if (ck + 1 < NC) { issue(ck + 1, p ^ 1); cp_wait1(); }
        else             { cp_wait0(); }
        __syncthreads();
        float* As = Asb[p];
        float* Bs = Bsb[p];
        #pragma unroll
        for (int kk = 0; kk < 4; kk++) {
            const int kb = kk * 8;
            uint32_t a[4][4];
            #pragma unroll
            for (int fm = 0; fm < 4; fm++) {
                int r0 = wm + fm * 16 + g;
                a[fm][0] = __float_as_uint(As[r0 * PAD + kb + t]);
                a[fm][1] = __float_as_uint(As[(r0 + 8) * PAD + kb + t]);
                a[fm][2] = __float_as_uint(As[r0 * PAD + kb + t + 4]);
                a[fm][3] = __float_as_uint(As[(r0 + 8) * PAD + kb + t + 4]);
            }
            #pragma unroll
            for (int nf = 0; nf < 8; nf++) {
                uint32_t b[2];
                int rn = wn + nf * 8 + g;
                b[0] = __float_as_uint(Bs[rn * PAD + kb + t]);
                b[1] = __float_as_uint(Bs[rn * PAD + kb + t + 4]);
                #pragma unroll
                for (int fm = 0; fm < 4; fm++)
                    mma_tf32(acc[fm][nf], a[fm], b);
            }
        }
        __syncthreads();
    }

    const int cbase = nblk * 128 + wn;
    #pragma unroll
    for (int fm = 0; fm < 4; fm++) {
        int row = bm + wm + fm * 16 + g;
        #pragma unroll
        for (int nf = 0; nf < 8; nf++) {
            int col = cbase + nf * 8 + 2 * t;
            float bv0 = __ldg(b1 + col), bv1 = __ldg(b1 + col + 1);
            if (row < NTOT) {
                __half2 hv = __floats2half2_rn(acc[fm][nf][0] + bv0, acc[fm][nf][1] + bv1);
                *(__half2*)(g_x2h + (size_t)row * 256 + col) = hv;
            }
            if (row + 8 < NTOT) {
                __half2 hv = __floats2half2_rn(acc[fm][nf][2] + bv0, acc[fm][nf][3] + bv1);
                *(__half2*)(g_x2h + (size_t)(row + 8) * 256 + col) = hv;
            }
        }
    }
}

// ---------------------------------------------------------------------------
// CSR SpMM over fp16 x2: out = A @ x2h, warp per row.
// ---------------------------------------------------------------------------
__global__ __launch_bounds__(256) void spmm_half(float* __restrict__ Y)
{
    const int row = blockIdx.x * 8 + (threadIdx.x >> 5);
    if (row >= NTOT) return;
    const int lane = threadIdx.x & 31;
    int e = g_rptr[row];
    const int e1 = g_rptr[row + 1];

    float acc[8];
    #pragma unroll
    for (int j = 0; j < 8; j++) acc[j] = 0.f;

    for (; e + 2 <= e1; e += 2) {
        const int   c0 = g_scol[e],     c1 = g_scol[e + 1];
        const float v0 = g_sval[e],     v1 = g_sval[e + 1];
        uint4 q0 = __ldg((const uint4*)(g_x2h + (size_t)c0 * 256) + lane);
        uint4 q1 = __ldg((const uint4*)(g_x2h + (size_t)c1 * 256) + lane);
        const __half2* h0 = (const __half2*)&q0;
        const __half2* h1 = (const __half2*)&q1;
        #pragma unroll
        for (int k = 0; k < 4; k++) {
            float2 f0 = __half22float2(h0[k]);
            float2 f1 = __half22float2(h1[k]);
            acc[2 * k]     += v0 * f0.x + v1 * f1.x;
            acc[2 * k + 1] += v0 * f0.y + v1 * f1.y;
        }
    }
    if (e < e1) {
        const int   c = g_scol[e];
        const float v = g_sval[e];
        uint4 q = __ldg((const uint4*)(g_x2h + (size_t)c * 256) + lane);
        const __half2* h = (const __half2*)&q;
        #pragma unroll
        for (int k = 0; k < 4; k++) {
            float2 f = __half22float2(h[k]);
            acc[2 * k]     += v * f.x;
            acc[2 * k + 1] += v * f.y;
        }
    }

    float* yp = Y + (size_t)row * 256 + lane * 8;
    *(float4*)yp       = make_float4(acc[0], acc[1], acc[2], acc[3]);
    *(float4*)(yp + 4) = make_float4(acc[4], acc[5], acc[6], acc[7]);
}

// ---------------------------------------------------------------------------
extern "C" void kernel_launch(void* const* d_in, const int* in_sizes, int n_in,
                              void* d_out, int out_size)
{
    const float* user_feat = (const float*)d_in[0];
    const float* item_feat = (const float*)d_in[1];
    const int*   edge_rows = (const int*)  d_in[2];
    const int*   edge_cols = (const int*)  d_in[3];
    const float* edge_vals = (const float*)d_in[4];
    const float* W0        = (const float*)d_in[5];
    const float* b0        = (const float*)d_in[6];
    const float* Wres0     = (const float*)d_in[7];
    const float* W1        = (const float*)d_in[8];
    const float* b1        = (const float*)d_in[9];
    float* out = (float*)d_out;

    cudaFuncSetAttribute(gemmh_mma, cudaFuncAttributeMaxDynamicSharedMemorySize, G_SMEM);
    cudaFuncSetAttribute(gemm1_mma, cudaFuncAttributeMaxDynamicSharedMemorySize, G_SMEM);

    const int n_mtiles = (NTOT + 127) / 128;  // 782
    const int eb = (N_EDGES + 255) / 256;
    const int rb = (NTOT + 7) / 8;

    // 1: weights -> tf32 transposed copies; also zeroes g_rcnt
    transpose_weights<<<256, 256>>>(W0, Wres0, W1);
    // 2-4: CSR build (scan also zeroes g_rcnt2)
    row_hist<<<eb, 256>>>(edge_rows);
    row_scan<<<1, 1024>>>();
    edge_scatter<<<eb, 256>>>(edge_rows, edge_cols, edge_vals);
    // 5: P = A @ feat, rowsum = A @ 1
    spmm_feat<<<rb, 256>>>(user_feat, item_feat);
    // 6: h = relu(P@W0 + feat@Wres + rowsum*b0)
    gemmh_mma<<<dim3(2, n_mtiles), 128, G_SMEM>>>(user_feat, item_feat, b0);
    // 7: x2h = fp16(h @ W1 + b1)
    gemm1_mma<<<dim3(2, n_mtiles), 128, G_SMEM>>>(b1);
    // 8: out = A @ x2h
    spmm_half<<<rb, 256>>>(out);
}

// round 15
// speedup vs baseline: 1.2133x; 1.2133x over previous
#include <cuda_runtime.h>
#include <cuda_fp16.h>
#include <cstdint>

#define N_USERS  40000
#define NTOT     100000
#define IN_DIM   128
#define HID      256
#define OUT_DIM  256
#define N_EDGES  600000

// Scratch (allocation-free rule: device globals)
__device__ __half g_fh [(size_t)NTOT * IN_DIM];   // feat, fp16
__device__ __half g_P  [(size_t)NTOT * IN_DIM];   // A @ feat, fp16
__device__ __half g_h  [(size_t)NTOT * HID];      // relu([P|F]@[W0;Wres] + rowsum*b0), fp16
__device__ __half g_x2h[(size_t)NTOT * OUT_DIM];  // h @ W1 + b1, fp16
__device__ float  g_rsum[NTOT];                   // A @ 1
__device__ __half g_WhT[HID * 256];               // [n][k]: k<128 -> W0[k][n], else Wres[k-128][n]
__device__ __half g_W1T[OUT_DIM * HID];           // W1^T
__device__ int    g_rcnt [NTOT];
__device__ int    g_rcnt2[NTOT];
__device__ int    g_rptr [NTOT + 1];
__device__ int    g_scol[N_EDGES];
__device__ float  g_sval[N_EDGES];

__device__ __forceinline__ void mma_f16(float* c, const uint32_t* a, const uint32_t* b) {
    asm volatile(
        "mma.sync.aligned.m16n8k16.row.col.f32.f16.f16.f32 "
        "{%0,%1,%2,%3}, {%4,%5,%6,%7}, {%8,%9}, {%0,%1,%2,%3};"
        : "+f"(c[0]), "+f"(c[1]), "+f"(c[2]), "+f"(c[3])
        : "r"(a[0]), "r"(a[1]), "r"(a[2]), "r"(a[3]), "r"(b[0]), "r"(b[1]));
}
__device__ __forceinline__ uint32_t smem_u32(const void* p) {
    uint32_t a;
    asm("{ .reg .u64 t; cvta.to.shared.u64 t, %1; cvt.u32.u64 %0, t; }" : "=r"(a) : "l"(p));
    return a;
}
__device__ __forceinline__ void cp16(uint32_t dst, const void* src, bool pred) {
    int sz = pred ? 16 : 0;
    asm volatile("cp.async.ca.shared.global [%0], [%1], 16, %2;"
                 :: "r"(dst), "l"(src), "r"(sz) : "memory");
}
__device__ __forceinline__ void cp_commit() {
    asm volatile("cp.async.commit_group;" ::: "memory");
}
__device__ __forceinline__ void cp_wait1() {
    asm volatile("cp.async.wait_group 1;" ::: "memory");
}
__device__ __forceinline__ void cp_wait0() {
    asm volatile("cp.async.wait_group 0;" ::: "memory");
}

#define PADH  40                   // halves per smem row (80B stride, conflict-free)
#define PADH2 20                   // half2 per row
#define TILEH (128 * PADH)         // 5120 halves per tile stage
#define G_SMEM (4 * TILEH * 2)     // 40960 B -> 2+ CTAs/SM

// ---------------------------------------------------------------------------
// Prep: weights -> fp16 K-major; feat -> fp16; zero g_rcnt.  65536 threads.
// ---------------------------------------------------------------------------
__global__ __launch_bounds__(256) void prep(
    const float* __restrict__ W0, const float* __restrict__ Wres,
    const float* __restrict__ W1,
    const float* __restrict__ uf, const float* __restrict__ itf) {
    int idx = blockIdx.x * 256 + threadIdx.x;   // 0..65535
    if (idx < IN_DIM * HID) {
        int k = idx / HID, n = idx % HID;
        g_WhT[n * 256 + k]       = __float2half(W0[idx]);
        g_WhT[n * 256 + 128 + k] = __float2half(Wres[idx]);
    }
    {   // W1: exactly 65536 elements
        int k = idx / OUT_DIM, n = idx % OUT_DIM;
        g_W1T[n * HID + k] = __float2half(W1[idx]);
    }
    for (int i = idx; i < NTOT; i += 65536) g_rcnt[i] = 0;
    // feat -> fp16 (float4 granularity: 3.2M slots)
    for (int s = idx; s < NTOT * (IN_DIM / 4); s += 65536) {
        int row = s >> 5;                 // 32 float4 per row
        int c4 = (s & 31) * 4;
        const float* src = (row < N_USERS) ? uf + (size_t)row * IN_DIM + c4
                                           : itf + (size_t)(row - N_USERS) * IN_DIM + c4;
        float4 v = __ldg((const float4*)src);
        __half2 h0 = __floats2half2_rn(v.x, v.y);
        __half2 h1 = __floats2half2_rn(v.z, v.w);
        uint2 u;
        u.x = *(uint32_t*)&h0;
        u.y = *(uint32_t*)&h1;
        *(uint2*)(g_fh + (size_t)row * IN_DIM + c4) = u;
    }
}

// ---------------------------------------------------------------------------
// CSR build
// ---------------------------------------------------------------------------
__global__ __launch_bounds__(256) void row_hist(const int* __restrict__ rows) {
    int e = blockIdx.x * 256 + threadIdx.x;
    if (e < N_EDGES) atomicAdd(&g_rcnt[rows[e]], 1);
}

#define CHUNK 98
__global__ __launch_bounds__(1024) void row_scan() {
    __shared__ int ssum[1024];
    const int tid = threadIdx.x;
    const int base = tid * CHUNK;
    int s = 0;
    #pragma unroll 7
    for (int i = 0; i < CHUNK; i++) {
        int idx = base + i;
        if (idx < NTOT) { s += g_rcnt[idx]; g_rcnt2[idx] = 0; }
    }
    ssum[tid] = s;
    __syncthreads();
    for (int d = 1; d < 1024; d <<= 1) {
        int o = (tid >= d) ? ssum[tid - d] : 0;
        __syncthreads();
        ssum[tid] += o;
        __syncthreads();
    }
    int run = ssum[tid] - s;
    #pragma unroll 7
    for (int i = 0; i < CHUNK; i++) {
        int idx = base + i;
        if (idx < NTOT) {
            g_rptr[idx] = run;
            run += g_rcnt[idx];
        }
    }
    if (tid == 1023) g_rptr[NTOT] = ssum[1023];
}

__global__ __launch_bounds__(256) void edge_scatter(
    const int* __restrict__ rows, const int* __restrict__ cols,
    const float* __restrict__ vals) {
    int e = blockIdx.x * 256 + threadIdx.x;
    if (e >= N_EDGES) return;
    int r = rows[e];
    int pos = g_rptr[r] + atomicAdd(&g_rcnt2[r], 1);
    g_scol[pos] = cols[e];
    g_sval[pos] = vals[e];
}

// ---------------------------------------------------------------------------
// spmmP: P = A @ feat_fp16 (8B gather/lane), rowsum = A @ 1. Warp per row.
// ---------------------------------------------------------------------------
__global__ __launch_bounds__(256) void spmm_feat()
{
    const int row = blockIdx.x * 8 + (threadIdx.x >> 5);
    if (row >= NTOT) return;
    const int lane = threadIdx.x & 31;
    int e = g_rptr[row];
    const int e1 = g_rptr[row + 1];

    float acc[4] = {0.f, 0.f, 0.f, 0.f};
    float rs = 0.f;

    for (; e + 4 <= e1; e += 4) {
        int   c[4];
        float v[4];
        #pragma unroll
        for (int q = 0; q < 4; q++) { c[q] = g_scol[e + q]; v[q] = g_sval[e + q]; }
        #pragma unroll
        for (int q = 0; q < 4; q++) {
            uint2 u = __ldg((const uint2*)(g_fh + (size_t)c[q] * IN_DIM) + lane);
            float2 f0 = __half22float2(*(__half2*)&u.x);
            float2 f1 = __half22float2(*(__half2*)&u.y);
            acc[0] += v[q] * f0.x; acc[1] += v[q] * f0.y;
            acc[2] += v[q] * f1.x; acc[3] += v[q] * f1.y;
            rs += v[q];
        }
    }
    for (; e < e1; e++) {
        const int c = g_scol[e];
        const float v = g_sval[e];
        uint2 u = __ldg((const uint2*)(g_fh + (size_t)c * IN_DIM) + lane);
        float2 f0 = __half22float2(*(__half2*)&u.x);
        float2 f1 = __half22float2(*(__half2*)&u.y);
        acc[0] += v * f0.x; acc[1] += v * f0.y;
        acc[2] += v * f1.x; acc[3] += v * f1.y;
        rs += v;
    }

    __half2 o0 = __floats2half2_rn(acc[0], acc[1]);
    __half2 o1 = __floats2half2_rn(acc[2], acc[3]);
    uint2 u;
    u.x = *(uint32_t*)&o0;
    u.y = *(uint32_t*)&o1;
    *((uint2*)(g_P + (size_t)row * IN_DIM) + lane) = u;
    if (lane == 0) g_rsum[row] = rs;
}

// ---------------------------------------------------------------------------
// gemm_h (fp16 mma m16n8k16, BM=128 BN=128 grid(2,·), 256 thr, warp 32x64):
//   h = fp16(relu([P|F] @ WhT + rowsum*b0))
// ---------------------------------------------------------------------------
__global__ __launch_bounds__(256, 2) void gemmh_mma(const float* __restrict__ b0)
{
    extern __shared__ __half smemh[];
    __half* Asb[2] = { smemh, smemh + TILEH };
    __half* Bsb[2] = { smemh + 2 * TILEH, smemh + 3 * TILEH };
    const uint32_t sb = smem_u32(smemh);

    const int tid = threadIdx.x, lane = tid & 31, wid = tid >> 5;
    const int wm = (wid & 3) * 32, wn = (wid >> 2) * 64;
    const int nblk = blockIdx.x;                 // 0..1
    const int bm = blockIdx.y * 128;
    const int g = lane >> 2, t = lane & 3;
    const int lr = tid >> 2;                     // row 0..63 (2 iters of 64)
    const int lq = tid & 3;                      // 16B chunk within 64B row-chunk

    float acc[2][8][4];
    #pragma unroll
    for (int i = 0; i < 2; i++)
        #pragma unroll
        for (int j = 0; j < 8; j++)
            #pragma unroll
            for (int q = 0; q < 4; q++) acc[i][j][q] = 0.f;

    const int NC = 8;   // K=256 halves, BK=32

    auto issue = [&](int ck, int p) {
        uint32_t a_s = sb + (uint32_t)((Asb[p] - smemh) * 2);
        uint32_t b_s = sb + (uint32_t)((Bsb[p] - smemh) * 2);
        #pragma unroll
        for (int i = 0; i < 2; i++) {            // A: 128 rows x 32 halves
            int r = i * 64 + lr;
            int rg = bm + r;
            bool ok = rg < NTOT;
            const __half* src;
            if (ck < 4) src = ok ? g_P  + (size_t)rg * IN_DIM + ck * 32 + lq * 8 : g_P;
            else        src = ok ? g_fh + (size_t)rg * IN_DIM + (ck - 4) * 32 + lq * 8 : g_fh;
            cp16(a_s + (uint32_t)(r * PADH + lq * 8) * 2, src, ok);
        }
        #pragma unroll
        for (int i = 0; i < 2; i++) {            // B: 128 rows x 32 halves
            int r = i * 64 + lr;
            cp16(b_s + (uint32_t)(r * PADH + lq * 8) * 2,
                 g_WhT + (size_t)(nblk * 128 + r) * 256 + ck * 32 + lq * 8, true);
        }
        cp_commit();
    };

    issue(0, 0);
    for (int ck = 0; ck < NC; ck++) {
        const int p = ck & 1;
        if (ck + 1 < NC) { issue(ck + 1, p ^ 1); cp_wait1(); }
        else             { cp_wait0(); }
        __syncthreads();
        const uint32_t* As32 = (const uint32_t*)Asb[p];
        const uint32_t* Bs32 = (const uint32_t*)Bsb[p];
        #pragma unroll
        for (int kk = 0; kk < 2; kk++) {         // two k16 slices per chunk
            const int kb2 = kk * 8;              // half2 offset
            uint32_t a[2][4];
            #pragma unroll
            for (int fm = 0; fm < 2; fm++) {
                int r0 = wm + fm * 16 + g;
                a[fm][0] = As32[r0 * PADH2 + kb2 + t];
                a[fm][1] = As32[(r0 + 8) * PADH2 + kb2 + t];
                a[fm][2] = As32[r0 * PADH2 + kb2 + t + 4];
                a[fm][3] = As32[(r0 + 8) * PADH2 + kb2 + t + 4];
            }
            #pragma unroll
            for (int nf = 0; nf < 8; nf++) {
                uint32_t b[2];
                int rn = wn + nf * 8 + g;
                b[0] = Bs32[rn * PADH2 + kb2 + t];
                b[1] = Bs32[rn * PADH2 + kb2 + t + 4];
                mma_f16(acc[0][nf], a[0], b);
                mma_f16(acc[1][nf], a[1], b);
            }
        }
        __syncthreads();
    }

    const int cbase = nblk * 128 + wn;
    #pragma unroll
    for (int fm = 0; fm < 2; fm++) {
        int row = bm + wm + fm * 16 + g;
        float rs0 = (row < NTOT)     ? __ldg(g_rsum + row)     : 0.f;
        float rs1 = (row + 8 < NTOT) ? __ldg(g_rsum + row + 8) : 0.f;
        #pragma unroll
        for (int nf = 0; nf < 8; nf++) {
            int col = cbase + nf * 8 + 2 * t;
            float bv0 = __ldg(b0 + col), bv1 = __ldg(b0 + col + 1);
            if (row < NTOT) {
                __half2 hv = __floats2half2_rn(fmaxf(acc[fm][nf][0] + rs0 * bv0, 0.f),
                                               fmaxf(acc[fm][nf][1] + rs0 * bv1, 0.f));
                *(__half2*)(g_h + (size_t)row * 256 + col) = hv;
            }
            if (row + 8 < NTOT) {
                __half2 hv = __floats2half2_rn(fmaxf(acc[fm][nf][2] + rs1 * bv0, 0.f),
                                               fmaxf(acc[fm][nf][3] + rs1 * bv1, 0.f));
                *(__half2*)(g_h + (size_t)(row + 8) * 256 + col) = hv;
            }
        }
    }
}

// ---------------------------------------------------------------------------
// GEMM1 (fp16 mma m16n8k16, same shape): x2h = fp16(h @ W1 + b1)
// ---------------------------------------------------------------------------
__global__ __launch_bounds__(256, 2) void gemm1_mma(const float* __restrict__ b1)
{
    extern __shared__ __half smemh[];
    __half* Asb[2] = { smemh, smemh + TILEH };
    __half* Bsb[2] = { smemh + 2 * TILEH, smemh + 3 * TILEH };
    const uint32_t sb = smem_u32(smemh);

    const int tid = threadIdx.x, lane = tid & 31, wid = tid >> 5;
    const int wm = (wid & 3) * 32, wn = (wid >> 2) * 64;
    const int nblk = blockIdx.x;                 // 0..1
    const int bm = blockIdx.y * 128;
    const int g = lane >> 2, t = lane & 3;
    const int lr = tid >> 2;
    const int lq = tid & 3;

    float acc[2][8][4];
    #pragma unroll
    for (int i = 0; i < 2; i++)
        #pragma unroll
        for (int j = 0; j < 8; j++)
            #pragma unroll
            for (int q = 0; q < 4; q++) acc[i][j][q] = 0.f;

    const int NC = 8;

    auto issue = [&](int ck, int p) {
        uint32_t a_s = sb + (uint32_t)((Asb[p] - smemh) * 2);
        uint32_t b_s = sb + (uint32_t)((Bsb[p] - smemh) * 2);
        #pragma unroll
        for (int i = 0; i < 2; i++) {
            int r = i * 64 + lr;
            int rg = bm + r;
            bool ok = rg < NTOT;
            const __half* src = ok ? g_h + (size_t)rg * HID + ck * 32 + lq * 8 : g_h;
            cp16(a_s + (uint32_t)(r * PADH + lq * 8) * 2, src, ok);
        }
        #pragma unroll
        for (int i = 0; i < 2; i++) {
            int r = i * 64 + lr;
            cp16(b_s + (uint32_t)(r * PADH + lq * 8) * 2,
                 g_W1T + (size_t)(nblk * 128 + r) * HID + ck * 32 + lq * 8, true);
        }
        cp_commit();
    };

    issue(0, 0);
    for (int ck = 0; ck < NC; ck++) {
        const int p = ck & 1;
        if (ck + 1 < NC) { issue(ck + 1, p ^ 1); cp_wait1(); }
        else             { cp_wait0(); }
        __syncthreads();
        const uint32_t* As32 = (const uint32_t*)Asb[p];
        const uint32_t* Bs32 = (const uint32_t*)Bsb[p];
        #pragma unroll
        for (int kk = 0; kk < 2; kk++) {
            const int kb2 = kk * 8;
            uint32_t a[2][4];
            #pragma unroll
            for (int fm = 0; fm < 2; fm++) {
                int r0 = wm + fm * 16 + g;
                a[fm][0] = As32[r0 * PADH2 + kb2 + t];
                a[fm][1] = As32[(r0 + 8) * PADH2 + kb2 + t];
                a[fm][2] = As32[r0 * PADH2 + kb2 + t + 4];
                a[fm][3] = As32[(r0 + 8) * PADH2 + kb2 + t + 4];
            }
            #pragma unroll
            for (int nf = 0; nf < 8; nf++) {
                uint32_t b[2];
                int rn = wn + nf * 8 + g;
                b[0] = Bs32[rn * PADH2 + kb2 + t];
                b[1] = Bs32[rn * PADH2 + kb2 + t + 4];
                mma_f16(acc[0][nf], a[0], b);
                mma_f16(acc[1][nf], a[1], b);
            }
        }
        __syncthreads();
    }

    const int cbase = nblk * 128 + wn;
    #pragma unroll
    for (int fm = 0; fm < 2; fm++) {
        int row = bm + wm + fm * 16 + g;
        #pragma unroll
        for (int nf = 0; nf < 8; nf++) {
            int col = cbase + nf * 8 + 2 * t;
            float bv0 = __ldg(b1 + col), bv1 = __ldg(b1 + col + 1);
            if (row < NTOT) {
                __half2 hv = __floats2half2_rn(acc[fm][nf][0] + bv0, acc[fm][nf][1] + bv1);
                *(__half2*)(g_x2h + (size_t)row * 256 + col) = hv;
            }
            if (row + 8 < NTOT) {
                __half2 hv = __floats2half2_rn(acc[fm][nf][2] + bv0, acc[fm][nf][3] + bv1);
                *(__half2*)(g_x2h + (size_t)(row + 8) * 256 + col) = hv;
            }
        }
    }
}

// ---------------------------------------------------------------------------
// CSR SpMM over fp16 x2: out = A @ x2h, warp per row. fp32 accumulate + out.
// ---------------------------------------------------------------------------
__global__ __launch_bounds__(256) void spmm_half(float* __restrict__ Y)
{
    const int row = blockIdx.x * 8 + (threadIdx.x >> 5);
    if (row >= NTOT) return;
    const int lane = threadIdx.x & 31;
    int e = g_rptr[row];
    const int e1 = g_rptr[row + 1];

    float acc[8];
    #pragma unroll
    for (int j = 0; j < 8; j++) acc[j] = 0.f;

    for (; e + 2 <= e1; e += 2) {
        const int   c0 = g_scol[e],     c1 = g_scol[e + 1];
        const float v0 = g_sval[e],     v1 = g_sval[e + 1];
        uint4 q0 = __ldg((const uint4*)(g_x2h + (size_t)c0 * 256) + lane);
        uint4 q1 = __ldg((const uint4*)(g_x2h + (size_t)c1 * 256) + lane);
        const __half2* h0 = (const __half2*)&q0;
        const __half2* h1 = (const __half2*)&q1;
        #pragma unroll
        for (int k = 0; k < 4; k++) {
            float2 f0 = __half22float2(h0[k]);
            float2 f1 = __half22float2(h1[k]);
            acc[2 * k]     += v0 * f0.x + v1 * f1.x;
            acc[2 * k + 1] += v0 * f0.y + v1 * f1.y;
        }
    }
    if (e < e1) {
        const int   c = g_scol[e];
        const float v = g_sval[e];
        uint4 q = __ldg((const uint4*)(g_x2h + (size_t)c * 256) + lane);
        const __half2* h = (const __half2*)&q;
        #pragma unroll
        for (int k = 0; k < 4; k++) {
            float2 f = __half22float2(h[k]);
            acc[2 * k]     += v * f.x;
            acc[2 * k + 1] += v * f.y;
        }
    }

    float* yp = Y + (size_t)row * 256 + lane * 8;
    *(float4*)yp       = make_float4(acc[0], acc[1], acc[2], acc[3]);
    *(float4*)(yp + 4) = make_float4(acc[4], acc[5], acc[6], acc[7]);
}

// ---------------------------------------------------------------------------
extern "C" void kernel_launch(void* const* d_in, const int* in_sizes, int n_in,
                              void* d_out, int out_size)
{
    const float* user_feat = (const float*)d_in[0];
    const float* item_feat = (const float*)d_in[1];
    const int*   edge_rows = (const int*)  d_in[2];
    const int*   edge_cols = (const int*)  d_in[3];
    const float* edge_vals = (const float*)d_in[4];
    const float* W0        = (const float*)d_in[5];
    const float* b0        = (const float*)d_in[6];
    const float* Wres0     = (const float*)d_in[7];
    const float* W1        = (const float*)d_in[8];
    const float* b1        = (const float*)d_in[9];
    float* out = (float*)d_out;

    cudaFuncSetAttribute(gemmh_mma, cudaFuncAttributeMaxDynamicSharedMemorySize, G_SMEM);
    cudaFuncSetAttribute(gemm1_mma, cudaFuncAttributeMaxDynamicSharedMemorySize, G_SMEM);

    const int n_mtiles = (NTOT + 127) / 128;  // 782
    const int eb = (N_EDGES + 255) / 256;
    const int rb = (NTOT + 7) / 8;

    // 1: weights+feat -> fp16; zero g_rcnt
    prep<<<256, 256>>>(W0, Wres0, W1, user_feat, item_feat);
    // 2-4: CSR build (scan also zeroes g_rcnt2)
    row_hist<<<eb, 256>>>(edge_rows);
    row_scan<<<1, 1024>>>();
    edge_scatter<<<eb, 256>>>(edge_rows, edge_cols, edge_vals);
    // 5: P = A @ feat, rowsum = A @ 1   (fp16 gather)
    spmm_feat<<<rb, 256>>>();
    // 6: h = fp16(relu(P@W0 + feat@Wres + rowsum*b0))   (fp16 HMMA)
    gemmh_mma<<<dim3(2, n_mtiles), 256, G_SMEM>>>(b0);
    // 7: x2h = fp16(h @ W1 + b1)   (fp16 HMMA)
    gemm1_mma<<<dim3(2, n_mtiles), 256, G_SMEM>>>(b1);
    // 8: out = A @ x2h
    spmm_half<<<rb, 256>>>(out);
}